// round 7
// baseline (speedup 1.0000x reference)
#include <cuda_runtime.h>
#include <cstddef>

#define IMG_H 128
#define IMG_W 128

// ---------------------------------------------------------------------------
// Single fused kernel.
//   Phase A (all threads): issue all 18 window loads (6 rows x 3 cols) into
//     registers -> MLP=18, latency hidden under phase B + syncthreads.
//   Phase B (warp 0 only): recompute the 8 GLT thresholds with XLA's exact
//     fp32 rounding order, then integer cutoffs ct[t] = #{k : x(k) < thr[t]}
//     (== first k with x(k) >= thr[t], since x(k) is strictly increasing).
//     Lane l tests candidates k = l*8..l*8+7; warp-sum via __reduce_add_sync.
//   Phase C: census code + 8 integer compares, 2x STG.128 per pixel.
// Block (32,8): 32x32 tile, 4 pixels/thread along y. Grid (4,4,B).
// ---------------------------------------------------------------------------
__global__ __launch_bounds__(256) void lbp_glt_kernel(
    const float* __restrict__ img, const float* __restrict__ lt,
    float* __restrict__ out) {
    __shared__ int s_ct[8];

    const int x  = blockIdx.x * 32 + threadIdx.x;
    const int y0 = blockIdx.y * 32 + threadIdx.y * 4;   // first of 4 rows
    const int b  = blockIdx.z;

    const float* base = img + (size_t)b * (IMG_H * IMG_W);
    const bool xm_ok = (x > 0);
    const bool xp_ok = (x < IMG_W - 1);

    // ---- Phase A: front-batched window loads (rows y0-1 .. y0+4) ----
    float v[6][3];
#pragma unroll
    for (int r = 0; r < 6; r++) {
        const int yy = y0 - 1 + r;
        if (yy >= 0 && yy < IMG_H) {
            const float* row = base + yy * IMG_W + x;
            v[r][1] = row[0];
            v[r][0] = xm_ok ? row[-1] : 0.0f;
            v[r][2] = xp_ok ? row[1]  : 0.0f;
        } else {
            v[r][0] = 0.0f; v[r][1] = 0.0f; v[r][2] = 0.0f;
        }
    }

    // ---- Phase B: warp 0 computes integer cutoffs (overlaps load latency) --
    if (threadIdx.y == 0) {
        const int lane = threadIdx.x;

        float p[8];
#pragma unroll
        for (int i = 0; i < 8; i++)
            p[i] = __fadd_rn(fmaxf(lt[i], 0.0f), 1e-5f);     // relu + 1e-5

        float S = p[0];                                       // sequential sum
#pragma unroll
        for (int i = 1; i < 8; i++) S = __fadd_rn(S, p[i]);

        float n[8];
#pragma unroll
        for (int i = 0; i < 8; i++) n[i] = __fdiv_rn(p[i], S);

        // cumsum via associative_scan tree order (n=8)
        float b0 = __fadd_rn(n[0], n[1]);
        float b1 = __fadd_rn(n[2], n[3]);
        float b2 = __fadd_rn(n[4], n[5]);
        float b3 = __fadd_rn(n[6], n[7]);
        float c0 = __fadd_rn(b0, b1);
        float c1 = __fadd_rn(b2, b3);
        float r[8];
        r[0] = n[0];
        r[1] = b0;
        r[2] = __fadd_rn(b0, n[2]);
        r[3] = c0;
        r[4] = __fadd_rn(c0, n[4]);
        r[5] = __fadd_rn(c0, b2);
        r[6] = __fadd_rn(__fadd_rn(c0, b2), n[6]);
        r[7] = __fadd_rn(c0, c1);

        // candidate values x(k) for k = lane*8 .. lane*8+7 (exact XLA rounding)
        const float C = (float)(1.0 / 127.5);
        float xv[8];
#pragma unroll
        for (int j = 0; j < 8; j++)
            xv[j] = __fsub_rn(__fmul_rn((float)(lane * 8 + j), C), 1.0f);

#pragma unroll
        for (int t = 0; t < 8; t++) {
            const float thr = __fsub_rn(__fmul_rn(r[t], 2.0f), 1.0f);
            int cnt = 0;
#pragma unroll
            for (int j = 0; j < 8; j++) cnt += (xv[j] < thr) ? 1 : 0;
            const int ct = __reduce_add_sync(0xffffffffu, cnt); // = cutoff k
            if (lane == t) s_ct[t] = ct;
        }
    }
    __syncthreads();   // overlaps with phase-A load latency for warps 1..7

    const int4 ct0 = *reinterpret_cast<const int4*>(&s_ct[0]);
    const int4 ct1 = *reinterpret_cast<const int4*>(&s_ct[4]);

    // ---- Phase C: census codes + threshold compares + stores ----
    float* op = out + (((size_t)b * IMG_H + y0) * IMG_W + x) * 8;

#pragma unroll
    for (int i = 0; i < 4; i++) {
        const float c = v[i + 1][1];
        // census code, _NEIGHBORS order, ties (>=) -> 1
        int code = (v[i][0]     >= c)
                 | ((v[i][1]     >= c) << 1)
                 | ((v[i][2]     >= c) << 2)
                 | ((v[i + 1][2] >= c) << 3)
                 | ((v[i + 2][2] >= c) << 4)
                 | ((v[i + 2][1] >= c) << 5)
                 | ((v[i + 2][0] >= c) << 6)
                 | ((v[i + 1][0] >= c) << 7);

        float4 o0, o1;
        o0.x = (code >= ct0.x) ? 1.0f : 0.0f;
        o0.y = (code >= ct0.y) ? 1.0f : 0.0f;
        o0.z = (code >= ct0.z) ? 1.0f : 0.0f;
        o0.w = (code >= ct0.w) ? 1.0f : 0.0f;
        o1.x = (code >= ct1.x) ? 1.0f : 0.0f;
        o1.y = (code >= ct1.y) ? 1.0f : 0.0f;
        o1.z = (code >= ct1.z) ? 1.0f : 0.0f;
        o1.w = (code >= ct1.w) ? 1.0f : 0.0f;

        float4* p4 = reinterpret_cast<float4*>(op + (size_t)i * IMG_W * 8);
        p4[0] = o0;
        p4[1] = o1;
    }
}

extern "C" void kernel_launch(void* const* d_in, const int* in_sizes, int n_in,
                              void* d_out, int out_size) {
    const float* images = (const float*)d_in[0];
    const float* latent = (const float*)d_in[1];
    float* out = (float*)d_out;

    const int B = in_sizes[0] / (IMG_H * IMG_W);

    dim3 block(32, 8, 1);
    dim3 grid(IMG_W / 32, IMG_H / 32, B);
    lbp_glt_kernel<<<grid, block>>>(images, latent, out);
}

// round 8
// speedup vs baseline: 1.4369x; 1.4369x over previous
#include <cuda_runtime.h>
#include <cstddef>

#define IMG_H 128
#define IMG_W 128

// Integer code cutoffs per threshold: out[...,t] = (code >= g_ct[t])
__device__ __align__(16) int g_ct[8];

// ---------------------------------------------------------------------------
// Prologue (parallel, proven in R5): thread k evaluates x(k) with XLA's exact
// fp32 rounding; min-k with x(k) >= thr[t] is the integer cutoff.
// ---------------------------------------------------------------------------
__global__ void glt_cutoffs_kernel(const float* __restrict__ lt) {
    __shared__ int s_ct[8];
    const int tid = threadIdx.x;          // 0..255 == candidate code k
    if (tid < 8) s_ct[tid] = 256;         // "never" sentinel
    __syncthreads();

    float p[8];
#pragma unroll
    for (int i = 0; i < 8; i++)
        p[i] = __fadd_rn(fmaxf(lt[i], 0.0f), 1e-5f);   // relu + 1e-5

    float S = p[0];                                     // sequential sum
#pragma unroll
    for (int i = 1; i < 8; i++) S = __fadd_rn(S, p[i]);

    float n[8];
#pragma unroll
    for (int i = 0; i < 8; i++) n[i] = __fdiv_rn(p[i], S);

    // cumsum via associative_scan tree order (n=8)
    float b0 = __fadd_rn(n[0], n[1]);
    float b1 = __fadd_rn(n[2], n[3]);
    float b2 = __fadd_rn(n[4], n[5]);
    float b3 = __fadd_rn(n[6], n[7]);
    float c0 = __fadd_rn(b0, b1);
    float c1 = __fadd_rn(b2, b3);
    float r[8];
    r[0] = n[0];
    r[1] = b0;
    r[2] = __fadd_rn(b0, n[2]);
    r[3] = c0;
    r[4] = __fadd_rn(c0, n[4]);
    r[5] = __fadd_rn(c0, b2);
    r[6] = __fadd_rn(__fadd_rn(c0, b2), n[6]);
    r[7] = __fadd_rn(c0, c1);

    const float C = (float)(1.0 / 127.5);
    const float x = __fsub_rn(__fmul_rn((float)tid, C), 1.0f); // mul, then sub

    const int lane = tid & 31;
#pragma unroll
    for (int t = 0; t < 8; t++) {
        const float thr = __fsub_rn(__fmul_rn(r[t], 2.0f), 1.0f);
        unsigned m = __ballot_sync(0xffffffffu, x >= thr);
        if (m && lane == (__ffs(m) - 1)) atomicMin(&s_ct[t], tid);
    }
    __syncthreads();
    if (tid < 8) g_ct[tid] = s_ct[tid];
}

// ---------------------------------------------------------------------------
// Main: one warp per image row. Lane L owns cols 4L..4L+3.
//   Loads : 3x LDG.128 per lane (rows y-1,y,y+1) -> 12 wavefronts/warp.
//   Halos : 6 SHFLs; lane 0 / lane 31 edges are the zero pad (warp spans row).
//   Codes : 4 per lane, packed into one uint32 (8-bit each).
//   Stores: 8 rounds of lane-contiguous STG.128; codes redistributed by SHFL
//           so float4 index (j*32+lane) of the row is written by lane.
// Block (32,8) = 8 rows; grid (16, 256).
// ---------------------------------------------------------------------------
__global__ __launch_bounds__(256) void lbp_glt_kernel(
    const float* __restrict__ img, float* __restrict__ out) {
    const unsigned FULL = 0xffffffffu;
    const int lane = threadIdx.x;
    const int y    = blockIdx.x * 8 + threadIdx.y;
    const int b    = blockIdx.y;

    const float* row = img + ((size_t)b * IMG_H + y) * IMG_W + lane * 4;

    // ---- front-batched loads: 3 x float4 (zero pad for OOB rows) ----
    const float4 Z = make_float4(0.f, 0.f, 0.f, 0.f);
    float4 t = Z, m, bo = Z;
    if (y > 0)         t  = *reinterpret_cast<const float4*>(row - IMG_W);
    m = *reinterpret_cast<const float4*>(row);
    if (y < IMG_H - 1) bo = *reinterpret_cast<const float4*>(row + IMG_W);

    // ---- column halos via shuffle (image border -> 0) ----
    float Lt = __shfl_up_sync(FULL, t.w, 1);
    float Lm = __shfl_up_sync(FULL, m.w, 1);
    float Lb = __shfl_up_sync(FULL, bo.w, 1);
    float Rt = __shfl_down_sync(FULL, t.x, 1);
    float Rm = __shfl_down_sync(FULL, m.x, 1);
    float Rb = __shfl_down_sync(FULL, bo.x, 1);
    if (lane == 0)  { Lt = 0.f; Lm = 0.f; Lb = 0.f; }
    if (lane == 31) { Rt = 0.f; Rm = 0.f; Rb = 0.f; }

    // 6-wide windows per row
    const float T[6] = {Lt, t.x, t.y, t.z, t.w, Rt};
    const float M[6] = {Lm, m.x, m.y, m.z, m.w, Rm};
    const float B[6] = {Lb, bo.x, bo.y, bo.z, bo.w, Rb};

    // ---- census codes for 4 pixels, packed 8 bits each ----
    unsigned pack = 0;
#pragma unroll
    for (int j = 0; j < 4; j++) {
        const float c = M[j + 1];
        // _NEIGHBORS order, ties (>=) -> 1
        unsigned code = (T[j]     >= c ? 1u   : 0u)
                      | (T[j + 1] >= c ? 2u   : 0u)
                      | (T[j + 2] >= c ? 4u   : 0u)
                      | (M[j + 2] >= c ? 8u   : 0u)
                      | (B[j + 2] >= c ? 16u  : 0u)
                      | (B[j + 1] >= c ? 32u  : 0u)
                      | (B[j]     >= c ? 64u  : 0u)
                      | (M[j]     >= c ? 128u : 0u);
        pack |= code << (j * 8);
    }

    // ---- cutoffs: this lane always compares against the same half ----
    const int4 ct_lo = *reinterpret_cast<const int4*>(&g_ct[0]);
    const int4 ct_hi = *reinterpret_cast<const int4*>(&g_ct[4]);
    const int4 ct = (lane & 1) ? ct_hi : ct_lo;

    // ---- 8 store rounds, each a lane-contiguous 512B STG.128 ----
    float4* orow = reinterpret_cast<float4*>(
        out + ((size_t)b * IMG_H + y) * (IMG_W * 8));
    const int src_lane = (lane >> 3);        // + j*4 per round
    const int byte_sh  = ((lane >> 1) & 3) * 8;

#pragma unroll
    for (int j = 0; j < 8; j++) {
        const unsigned pk = __shfl_sync(FULL, pack, j * 4 + src_lane);
        const int code = (int)((pk >> byte_sh) & 0xffu);
        float4 o;
        o.x = (code >= ct.x) ? 1.0f : 0.0f;
        o.y = (code >= ct.y) ? 1.0f : 0.0f;
        o.z = (code >= ct.z) ? 1.0f : 0.0f;
        o.w = (code >= ct.w) ? 1.0f : 0.0f;
        orow[j * 32 + lane] = o;
    }
}

extern "C" void kernel_launch(void* const* d_in, const int* in_sizes, int n_in,
                              void* d_out, int out_size) {
    const float* images = (const float*)d_in[0];
    const float* latent = (const float*)d_in[1];
    float* out = (float*)d_out;

    const int B = in_sizes[0] / (IMG_H * IMG_W);

    glt_cutoffs_kernel<<<1, 256>>>(latent);

    dim3 block(32, 8, 1);
    dim3 grid(IMG_H / 8, B, 1);
    lbp_glt_kernel<<<grid, block>>>(images, out);
}

// round 9
// speedup vs baseline: 1.4667x; 1.0208x over previous
#include <cuda_runtime.h>
#include <cstddef>

#define IMG_H 128
#define IMG_W 128

// Integer code cutoffs per threshold: out[...,t] = (code >= g_ct[t])
__device__ __align__(16) int g_ct[8];

// ---------------------------------------------------------------------------
// Prologue: thread k evaluates x(k) with XLA's exact fp32 rounding; min-k with
// x(k) >= thr[t] is the integer cutoff. Triggers PDL completion as soon as
// g_ct is globally visible, so the main kernel's wait releases early.
// ---------------------------------------------------------------------------
__global__ void glt_cutoffs_kernel(const float* __restrict__ lt) {
    __shared__ int s_ct[8];
    const int tid = threadIdx.x;          // 0..255 == candidate code k
    if (tid < 8) s_ct[tid] = 256;         // "never" sentinel
    __syncthreads();

    float p[8];
#pragma unroll
    for (int i = 0; i < 8; i++)
        p[i] = __fadd_rn(fmaxf(lt[i], 0.0f), 1e-5f);   // relu + 1e-5

    float S = p[0];                                     // sequential sum
#pragma unroll
    for (int i = 1; i < 8; i++) S = __fadd_rn(S, p[i]);

    float n[8];
#pragma unroll
    for (int i = 0; i < 8; i++) n[i] = __fdiv_rn(p[i], S);

    // cumsum via associative_scan tree order (n=8)
    float b0 = __fadd_rn(n[0], n[1]);
    float b1 = __fadd_rn(n[2], n[3]);
    float b2 = __fadd_rn(n[4], n[5]);
    float b3 = __fadd_rn(n[6], n[7]);
    float c0 = __fadd_rn(b0, b1);
    float c1 = __fadd_rn(b2, b3);
    float r[8];
    r[0] = n[0];
    r[1] = b0;
    r[2] = __fadd_rn(b0, n[2]);
    r[3] = c0;
    r[4] = __fadd_rn(c0, n[4]);
    r[5] = __fadd_rn(c0, b2);
    r[6] = __fadd_rn(__fadd_rn(c0, b2), n[6]);
    r[7] = __fadd_rn(c0, c1);

    const float C = (float)(1.0 / 127.5);
    const float x = __fsub_rn(__fmul_rn((float)tid, C), 1.0f); // mul, then sub

    const int lane = tid & 31;
#pragma unroll
    for (int t = 0; t < 8; t++) {
        const float thr = __fsub_rn(__fmul_rn(r[t], 2.0f), 1.0f);
        unsigned m = __ballot_sync(0xffffffffu, x >= thr);
        if (m && lane == (__ffs(m) - 1)) atomicMin(&s_ct[t], tid);
    }
    __syncthreads();
    if (tid < 8) g_ct[tid] = s_ct[tid];

    // make g_ct globally visible, then release the dependent grid early
    __threadfence();
    cudaTriggerProgrammaticLaunchCompletion();
}

// ---------------------------------------------------------------------------
// Main (unchanged from R7 winner, plus PDL gate): one warp per image row.
//   Loads : 3x LDG.128 per lane (rows y-1,y,y+1), issued BEFORE the PDL wait.
//   Halos : 6 SHFLs; lane 0 / lane 31 edges are the zero pad.
//   Codes : 4 per lane, packed 8-bit into one uint32.
//   Stores: 8 rounds of lane-contiguous STG.128 via SHFL redistribution.
// Block (32,8) = 8 rows; grid (16, 256).
// ---------------------------------------------------------------------------
__global__ __launch_bounds__(256) void lbp_glt_kernel(
    const float* __restrict__ img, float* __restrict__ out) {
    const unsigned FULL = 0xffffffffu;
    const int lane = threadIdx.x;
    const int y    = blockIdx.x * 8 + threadIdx.y;
    const int b    = blockIdx.y;

    const float* row = img + ((size_t)b * IMG_H + y) * IMG_W + lane * 4;

    // ---- front-batched loads: 3 x float4 (zero pad for OOB rows) ----
    const float4 Z = make_float4(0.f, 0.f, 0.f, 0.f);
    float4 t = Z, m, bo = Z;
    if (y > 0)         t  = *reinterpret_cast<const float4*>(row - IMG_W);
    m = *reinterpret_cast<const float4*>(row);
    if (y < IMG_H - 1) bo = *reinterpret_cast<const float4*>(row + IMG_W);

    // ---- column halos via shuffle (image border -> 0) ----
    float Lt = __shfl_up_sync(FULL, t.w, 1);
    float Lm = __shfl_up_sync(FULL, m.w, 1);
    float Lb = __shfl_up_sync(FULL, bo.w, 1);
    float Rt = __shfl_down_sync(FULL, t.x, 1);
    float Rm = __shfl_down_sync(FULL, m.x, 1);
    float Rb = __shfl_down_sync(FULL, bo.x, 1);
    if (lane == 0)  { Lt = 0.f; Lm = 0.f; Lb = 0.f; }
    if (lane == 31) { Rt = 0.f; Rm = 0.f; Rb = 0.f; }

    // 6-wide windows per row
    const float T[6] = {Lt, t.x, t.y, t.z, t.w, Rt};
    const float M[6] = {Lm, m.x, m.y, m.z, m.w, Rm};
    const float B[6] = {Lb, bo.x, bo.y, bo.z, bo.w, Rb};

    // ---- census codes for 4 pixels, packed 8 bits each ----
    unsigned pack = 0;
#pragma unroll
    for (int j = 0; j < 4; j++) {
        const float c = M[j + 1];
        // _NEIGHBORS order, ties (>=) -> 1
        unsigned code = (T[j]     >= c ? 1u   : 0u)
                      | (T[j + 1] >= c ? 2u   : 0u)
                      | (T[j + 2] >= c ? 4u   : 0u)
                      | (M[j + 2] >= c ? 8u   : 0u)
                      | (B[j + 2] >= c ? 16u  : 0u)
                      | (B[j + 1] >= c ? 32u  : 0u)
                      | (B[j]     >= c ? 64u  : 0u)
                      | (M[j]     >= c ? 128u : 0u);
        pack |= code << (j * 8);
    }

    // ---- PDL gate: prologue's g_ct must be visible past this point ----
    cudaGridDependencySynchronize();

    // ---- cutoffs: this lane always compares against the same half ----
    const int4 ct_lo = *reinterpret_cast<const int4*>(&g_ct[0]);
    const int4 ct_hi = *reinterpret_cast<const int4*>(&g_ct[4]);
    const int4 ct = (lane & 1) ? ct_hi : ct_lo;

    // ---- 8 store rounds, each a lane-contiguous 512B STG.128 ----
    float4* orow = reinterpret_cast<float4*>(
        out + ((size_t)b * IMG_H + y) * (IMG_W * 8));
    const int src_lane = (lane >> 3);        // + j*4 per round
    const int byte_sh  = ((lane >> 1) & 3) * 8;

#pragma unroll
    for (int j = 0; j < 8; j++) {
        const unsigned pk = __shfl_sync(FULL, pack, j * 4 + src_lane);
        const int code = (int)((pk >> byte_sh) & 0xffu);
        float4 o;
        o.x = (code >= ct.x) ? 1.0f : 0.0f;
        o.y = (code >= ct.y) ? 1.0f : 0.0f;
        o.z = (code >= ct.z) ? 1.0f : 0.0f;
        o.w = (code >= ct.w) ? 1.0f : 0.0f;
        orow[j * 32 + lane] = o;
    }
}

extern "C" void kernel_launch(void* const* d_in, const int* in_sizes, int n_in,
                              void* d_out, int out_size) {
    const float* images = (const float*)d_in[0];
    const float* latent = (const float*)d_in[1];
    float* out = (float*)d_out;

    const int B = in_sizes[0] / (IMG_H * IMG_W);

    // Node 1: prologue (normal launch on the capture stream)
    glt_cutoffs_kernel<<<1, 256>>>(latent);

    // Node 2: main kernel, launched with programmatic stream serialization so
    // its launch overlaps the prologue; cudaGridDependencySynchronize() inside
    // the kernel enforces the g_ct dependency.
    cudaLaunchConfig_t cfg = {};
    cfg.gridDim  = dim3(IMG_H / 8, B, 1);
    cfg.blockDim = dim3(32, 8, 1);
    cfg.dynamicSmemBytes = 0;
    cfg.stream = 0;  // legacy default stream (same as <<<>>> above)

    cudaLaunchAttribute attr[1];
    attr[0].id = cudaLaunchAttributeProgrammaticStreamSerialization;
    attr[0].val.programmaticStreamSerializationAllowed = 1;
    cfg.attrs = attr;
    cfg.numAttrs = 1;

    cudaLaunchKernelEx(&cfg, lbp_glt_kernel, images, out);
}

// round 10
// speedup vs baseline: 1.5678x; 1.0689x over previous
#include <cuda_runtime.h>
#include <cstddef>

#define IMG_H 128
#define IMG_W 128

// ---------------------------------------------------------------------------
// Single fused kernel. Each warp handles TWO image rows (y0, y0+1) of one
// batch image and independently recomputes the 8 GLT integer cutoffs
// (no smem, no __syncthreads, ~90 issue slots/warp, overlapped with loads).
//
// Cutoffs: ct[t] = min{k in 0..255 : x(k) >= thr[t]}, else 256, where
// x(k) = fl(fl(k*C) - 1), C = fl(1/127.5) — exact XLA rounding. Instead of a
// 256-candidate scan, invert analytically: g = (thr+1)*127.5 locates the
// cutoff to within +-0.01, and an 8-candidate window [g-3, g+4] with exact
// x(k) evaluation gives the exact min k.
//
// Main body = R7/R8 proven structure: float4 loads, shuffle halos, packed
// 8-bit codes, 8 lane-contiguous STG.128 rounds per row.
// Block (32,8) = 16 rows; grid (8, 256).
// ---------------------------------------------------------------------------
__global__ __launch_bounds__(256) void lbp_glt_fused_kernel(
    const float* __restrict__ img, const float* __restrict__ lt,
    float* __restrict__ out) {
    const unsigned FULL = 0xffffffffu;
    const int lane = threadIdx.x;
    const int y0   = (blockIdx.x * 8 + threadIdx.y) * 2;   // rows y0, y0+1
    const int b    = blockIdx.y;

    // ---- issue lt loads first (broadcast across lanes; feeds cutoff math) --
    const float4 ltA = *reinterpret_cast<const float4*>(lt);
    const float4 ltB = *reinterpret_cast<const float4*>(lt + 4);

    // ---- front-batched image loads: rows y0-1 .. y0+2 (zero pad OOB) ----
    const float* row = img + ((size_t)b * IMG_H + y0) * IMG_W + lane * 4;
    const float4 Z = make_float4(0.f, 0.f, 0.f, 0.f);
    float4 r0 = Z, r1, r2, r3 = Z;
    if (y0 > 0)              r0 = *reinterpret_cast<const float4*>(row - IMG_W);
    r1 = *reinterpret_cast<const float4*>(row);
    r2 = *reinterpret_cast<const float4*>(row + IMG_W);      // y0+1 <= 127
    if (y0 + 2 < IMG_H)      r3 = *reinterpret_cast<const float4*>(row + 2 * IMG_W);

    // ---- cutoff math (lane-redundant; overlaps image load latency) ----
    float p[8];
    p[0] = __fadd_rn(fmaxf(ltA.x, 0.0f), 1e-5f);
    p[1] = __fadd_rn(fmaxf(ltA.y, 0.0f), 1e-5f);
    p[2] = __fadd_rn(fmaxf(ltA.z, 0.0f), 1e-5f);
    p[3] = __fadd_rn(fmaxf(ltA.w, 0.0f), 1e-5f);
    p[4] = __fadd_rn(fmaxf(ltB.x, 0.0f), 1e-5f);
    p[5] = __fadd_rn(fmaxf(ltB.y, 0.0f), 1e-5f);
    p[6] = __fadd_rn(fmaxf(ltB.z, 0.0f), 1e-5f);
    p[7] = __fadd_rn(fmaxf(ltB.w, 0.0f), 1e-5f);

    float S = p[0];                                       // sequential sum
#pragma unroll
    for (int i = 1; i < 8; i++) S = __fadd_rn(S, p[i]);

    float n[8];
#pragma unroll
    for (int i = 0; i < 8; i++) n[i] = __fdiv_rn(p[i], S);

    // cumsum via associative_scan tree order (n=8)
    const float b0 = __fadd_rn(n[0], n[1]);
    const float b1 = __fadd_rn(n[2], n[3]);
    const float b2 = __fadd_rn(n[4], n[5]);
    const float b3 = __fadd_rn(n[6], n[7]);
    const float c0 = __fadd_rn(b0, b1);
    const float c1 = __fadd_rn(b2, b3);
    float r[8];
    r[0] = n[0];
    r[1] = b0;
    r[2] = __fadd_rn(b0, n[2]);
    r[3] = c0;
    r[4] = __fadd_rn(c0, n[4]);
    r[5] = __fadd_rn(c0, b2);
    r[6] = __fadd_rn(__fadd_rn(c0, b2), n[6]);
    r[7] = __fadd_rn(c0, c1);

    // this lane resolves threshold t = lane & 7
    const int   t   = lane & 7;
    const float thr = __fsub_rn(__fmul_rn(r[t], 2.0f), 1.0f);
    const float C   = (float)(1.0 / 127.5);
    const float gf  = __fmul_rn(__fadd_rn(thr, 1.0f), 127.5f);
    int lo = (int)floorf(gf) - 3;
    if (lo < 0) lo = 0;
    int ctv = 256;                                        // "never" sentinel
#pragma unroll
    for (int j = 0; j < 8; j++) {
        const int   k  = lo + j;
        const float xk = __fsub_rn(__fmul_rn((float)k, C), 1.0f); // exact x(k)
        if (k <= 255 && xk >= thr && k < ctv) ctv = k;
    }
    // gather this lane's int4 of cutoffs (even lanes ct[0..3], odd ct[4..7])
    const int base = (lane & 1) * 4;
    int4 ct;
    ct.x = __shfl_sync(FULL, ctv, base + 0);
    ct.y = __shfl_sync(FULL, ctv, base + 1);
    ct.z = __shfl_sync(FULL, ctv, base + 2);
    ct.w = __shfl_sync(FULL, ctv, base + 3);

    // ---- column halos via shuffle (image border -> 0) ----
    float L0 = __shfl_up_sync(FULL, r0.w, 1);
    float L1 = __shfl_up_sync(FULL, r1.w, 1);
    float L2 = __shfl_up_sync(FULL, r2.w, 1);
    float L3 = __shfl_up_sync(FULL, r3.w, 1);
    float R0 = __shfl_down_sync(FULL, r0.x, 1);
    float R1 = __shfl_down_sync(FULL, r1.x, 1);
    float R2 = __shfl_down_sync(FULL, r2.x, 1);
    float R3 = __shfl_down_sync(FULL, r3.x, 1);
    if (lane == 0)  { L0 = 0.f; L1 = 0.f; L2 = 0.f; L3 = 0.f; }
    if (lane == 31) { R0 = 0.f; R1 = 0.f; R2 = 0.f; R3 = 0.f; }

    const float W0[6] = {L0, r0.x, r0.y, r0.z, r0.w, R0};
    const float W1[6] = {L1, r1.x, r1.y, r1.z, r1.w, R1};
    const float W2[6] = {L2, r2.x, r2.y, r2.z, r2.w, R2};
    const float W3[6] = {L3, r3.x, r3.y, r3.z, r3.w, R3};

    // ---- census codes, 4 px per row packed 8-bit; _NEIGHBORS order ----
    auto census4 = [&](const float* T, const float* M, const float* B) {
        unsigned pk = 0;
#pragma unroll
        for (int j = 0; j < 4; j++) {
            const float c = M[j + 1];
            unsigned code = (T[j]     >= c ? 1u   : 0u)
                          | (T[j + 1] >= c ? 2u   : 0u)
                          | (T[j + 2] >= c ? 4u   : 0u)
                          | (M[j + 2] >= c ? 8u   : 0u)
                          | (B[j + 2] >= c ? 16u  : 0u)
                          | (B[j + 1] >= c ? 32u  : 0u)
                          | (B[j]     >= c ? 64u  : 0u)
                          | (M[j]     >= c ? 128u : 0u);
            pk |= code << (j * 8);
        }
        return pk;
    };
    const unsigned packA = census4(W0, W1, W2);   // row y0
    const unsigned packB = census4(W1, W2, W3);   // row y0+1

    // ---- stores: 8 lane-contiguous STG.128 rounds per row ----
    float4* orow = reinterpret_cast<float4*>(
        out + ((size_t)b * IMG_H + y0) * (IMG_W * 8));
    const int src_lane = (lane >> 3);             // + j*4 per round
    const int byte_sh  = ((lane >> 1) & 3) * 8;

    auto store_row = [&](unsigned pack, float4* dst) {
#pragma unroll
        for (int j = 0; j < 8; j++) {
            const unsigned pk = __shfl_sync(FULL, pack, j * 4 + src_lane);
            const int code = (int)((pk >> byte_sh) & 0xffu);
            float4 o;
            o.x = (code >= ct.x) ? 1.0f : 0.0f;
            o.y = (code >= ct.y) ? 1.0f : 0.0f;
            o.z = (code >= ct.z) ? 1.0f : 0.0f;
            o.w = (code >= ct.w) ? 1.0f : 0.0f;
            dst[j * 32 + lane] = o;
        }
    };
    store_row(packA, orow);
    store_row(packB, orow + IMG_W * 8 / 4);       // next row: 256 float4s

}

extern "C" void kernel_launch(void* const* d_in, const int* in_sizes, int n_in,
                              void* d_out, int out_size) {
    const float* images = (const float*)d_in[0];
    const float* latent = (const float*)d_in[1];
    float* out = (float*)d_out;

    const int B = in_sizes[0] / (IMG_H * IMG_W);

    dim3 block(32, 8, 1);
    dim3 grid(IMG_H / 16, B, 1);
    lbp_glt_fused_kernel<<<grid, block>>>(images, latent, out);
}

// round 11
// speedup vs baseline: 1.8020x; 1.1494x over previous
#include <cuda_runtime.h>
#include <cstddef>

#define IMG_H 128
#define IMG_W 128

// ---------------------------------------------------------------------------
// Single fused kernel (R9 winner + evict-first stores). Each warp handles TWO
// image rows (y0, y0+1) of one batch image and independently recomputes the 8
// GLT integer cutoffs (no smem, no __syncthreads, overlapped with loads).
//
// Cutoffs: ct[t] = min{k in 0..255 : x(k) >= thr[t]}, else 256, where
// x(k) = fl(fl(k*C) - 1), C = fl(1/127.5) — exact XLA rounding. Analytic
// inversion g = (thr+1)*127.5 locates the cutoff to within +-0.01; the
// 8-candidate window [g-3, g+4] with exact x(k) evaluation gives exact min k.
//
// Stores use __stcs (evict_first): the 134 MB write-once output is marked
// streaming so L2 drains it to DRAM during the kernel window instead of
// back-loading the drain into the inter-replay gap.
// Block (32,8) = 16 rows; grid (8, 256).
// ---------------------------------------------------------------------------
__global__ __launch_bounds__(256) void lbp_glt_fused_kernel(
    const float* __restrict__ img, const float* __restrict__ lt,
    float* __restrict__ out) {
    const unsigned FULL = 0xffffffffu;
    const int lane = threadIdx.x;
    const int y0   = (blockIdx.x * 8 + threadIdx.y) * 2;   // rows y0, y0+1
    const int b    = blockIdx.y;

    // ---- issue lt loads first (broadcast across lanes; feeds cutoff math) --
    const float4 ltA = *reinterpret_cast<const float4*>(lt);
    const float4 ltB = *reinterpret_cast<const float4*>(lt + 4);

    // ---- front-batched image loads: rows y0-1 .. y0+2 (zero pad OOB) ----
    const float* row = img + ((size_t)b * IMG_H + y0) * IMG_W + lane * 4;
    const float4 Z = make_float4(0.f, 0.f, 0.f, 0.f);
    float4 r0 = Z, r1, r2, r3 = Z;
    if (y0 > 0)              r0 = *reinterpret_cast<const float4*>(row - IMG_W);
    r1 = *reinterpret_cast<const float4*>(row);
    r2 = *reinterpret_cast<const float4*>(row + IMG_W);      // y0+1 <= 127
    if (y0 + 2 < IMG_H)      r3 = *reinterpret_cast<const float4*>(row + 2 * IMG_W);

    // ---- cutoff math (lane-redundant; overlaps image load latency) ----
    float p[8];
    p[0] = __fadd_rn(fmaxf(ltA.x, 0.0f), 1e-5f);
    p[1] = __fadd_rn(fmaxf(ltA.y, 0.0f), 1e-5f);
    p[2] = __fadd_rn(fmaxf(ltA.z, 0.0f), 1e-5f);
    p[3] = __fadd_rn(fmaxf(ltA.w, 0.0f), 1e-5f);
    p[4] = __fadd_rn(fmaxf(ltB.x, 0.0f), 1e-5f);
    p[5] = __fadd_rn(fmaxf(ltB.y, 0.0f), 1e-5f);
    p[6] = __fadd_rn(fmaxf(ltB.z, 0.0f), 1e-5f);
    p[7] = __fadd_rn(fmaxf(ltB.w, 0.0f), 1e-5f);

    float S = p[0];                                       // sequential sum
#pragma unroll
    for (int i = 1; i < 8; i++) S = __fadd_rn(S, p[i]);

    float n[8];
#pragma unroll
    for (int i = 0; i < 8; i++) n[i] = __fdiv_rn(p[i], S);

    // cumsum via associative_scan tree order (n=8)
    const float b0 = __fadd_rn(n[0], n[1]);
    const float b1 = __fadd_rn(n[2], n[3]);
    const float b2 = __fadd_rn(n[4], n[5]);
    const float b3 = __fadd_rn(n[6], n[7]);
    const float c0 = __fadd_rn(b0, b1);
    const float c1 = __fadd_rn(b2, b3);
    float r[8];
    r[0] = n[0];
    r[1] = b0;
    r[2] = __fadd_rn(b0, n[2]);
    r[3] = c0;
    r[4] = __fadd_rn(c0, n[4]);
    r[5] = __fadd_rn(c0, b2);
    r[6] = __fadd_rn(__fadd_rn(c0, b2), n[6]);
    r[7] = __fadd_rn(c0, c1);

    // this lane resolves threshold t = lane & 7
    const int   t   = lane & 7;
    const float thr = __fsub_rn(__fmul_rn(r[t], 2.0f), 1.0f);
    const float C   = (float)(1.0 / 127.5);
    const float gf  = __fmul_rn(__fadd_rn(thr, 1.0f), 127.5f);
    int lo = (int)floorf(gf) - 3;
    if (lo < 0) lo = 0;
    int ctv = 256;                                        // "never" sentinel
#pragma unroll
    for (int j = 0; j < 8; j++) {
        const int   k  = lo + j;
        const float xk = __fsub_rn(__fmul_rn((float)k, C), 1.0f); // exact x(k)
        if (k <= 255 && xk >= thr && k < ctv) ctv = k;
    }
    // gather this lane's int4 of cutoffs (even lanes ct[0..3], odd ct[4..7])
    const int base = (lane & 1) * 4;
    int4 ct;
    ct.x = __shfl_sync(FULL, ctv, base + 0);
    ct.y = __shfl_sync(FULL, ctv, base + 1);
    ct.z = __shfl_sync(FULL, ctv, base + 2);
    ct.w = __shfl_sync(FULL, ctv, base + 3);

    // ---- column halos via shuffle (image border -> 0) ----
    float L0 = __shfl_up_sync(FULL, r0.w, 1);
    float L1 = __shfl_up_sync(FULL, r1.w, 1);
    float L2 = __shfl_up_sync(FULL, r2.w, 1);
    float L3 = __shfl_up_sync(FULL, r3.w, 1);
    float R0 = __shfl_down_sync(FULL, r0.x, 1);
    float R1 = __shfl_down_sync(FULL, r1.x, 1);
    float R2 = __shfl_down_sync(FULL, r2.x, 1);
    float R3 = __shfl_down_sync(FULL, r3.x, 1);
    if (lane == 0)  { L0 = 0.f; L1 = 0.f; L2 = 0.f; L3 = 0.f; }
    if (lane == 31) { R0 = 0.f; R1 = 0.f; R2 = 0.f; R3 = 0.f; }

    const float W0[6] = {L0, r0.x, r0.y, r0.z, r0.w, R0};
    const float W1[6] = {L1, r1.x, r1.y, r1.z, r1.w, R1};
    const float W2[6] = {L2, r2.x, r2.y, r2.z, r2.w, R2};
    const float W3[6] = {L3, r3.x, r3.y, r3.z, r3.w, R3};

    // ---- census codes, 4 px per row packed 8-bit; _NEIGHBORS order ----
    auto census4 = [&](const float* T, const float* M, const float* B) {
        unsigned pk = 0;
#pragma unroll
        for (int j = 0; j < 4; j++) {
            const float c = M[j + 1];
            unsigned code = (T[j]     >= c ? 1u   : 0u)
                          | (T[j + 1] >= c ? 2u   : 0u)
                          | (T[j + 2] >= c ? 4u   : 0u)
                          | (M[j + 2] >= c ? 8u   : 0u)
                          | (B[j + 2] >= c ? 16u  : 0u)
                          | (B[j + 1] >= c ? 32u  : 0u)
                          | (B[j]     >= c ? 64u  : 0u)
                          | (M[j]     >= c ? 128u : 0u);
            pk |= code << (j * 8);
        }
        return pk;
    };
    const unsigned packA = census4(W0, W1, W2);   // row y0
    const unsigned packB = census4(W1, W2, W3);   // row y0+1

    // ---- stores: 8 lane-contiguous STG.128 (evict-first) rounds per row ----
    float4* orow = reinterpret_cast<float4*>(
        out + ((size_t)b * IMG_H + y0) * (IMG_W * 8));
    const int src_lane = (lane >> 3);             // + j*4 per round
    const int byte_sh  = ((lane >> 1) & 3) * 8;

    auto store_row = [&](unsigned pack, float4* dst) {
#pragma unroll
        for (int j = 0; j < 8; j++) {
            const unsigned pk = __shfl_sync(FULL, pack, j * 4 + src_lane);
            const int code = (int)((pk >> byte_sh) & 0xffu);
            float4 o;
            o.x = (code >= ct.x) ? 1.0f : 0.0f;
            o.y = (code >= ct.y) ? 1.0f : 0.0f;
            o.z = (code >= ct.z) ? 1.0f : 0.0f;
            o.w = (code >= ct.w) ? 1.0f : 0.0f;
            __stcs(&dst[j * 32 + lane], o);       // streaming: evict-first
        }
    };
    store_row(packA, orow);
    store_row(packB, orow + IMG_W * 8 / 4);       // next row: 256 float4s
}

extern "C" void kernel_launch(void* const* d_in, const int* in_sizes, int n_in,
                              void* d_out, int out_size) {
    const float* images = (const float*)d_in[0];
    const float* latent = (const float*)d_in[1];
    float* out = (float*)d_out;

    const int B = in_sizes[0] / (IMG_H * IMG_W);

    dim3 block(32, 8, 1);
    dim3 grid(IMG_H / 16, B, 1);
    lbp_glt_fused_kernel<<<grid, block>>>(images, latent, out);
}